// round 15
// baseline (speedup 1.0000x reference)
#include <cuda_runtime.h>
#include <cuda_fp16.h>
#include <math.h>
#include <stdint.h>

// ---------------- problem constants ----------------
#define NH   10
#define BSZ  16384
#define DD   2048      // D1 == D21 == D22
#define BM   128
#define BN   128
#define BK   64
#define NS   (DD/BK)   // 32 k-stages
#define STAGE_BYTES 32768   // A 16KB + B 16KB per stage
#define RED_OFF   (3 * STAGE_BYTES)       // epilogue reduction buffer (separate from stages)
#define GEMM_SMEM (RED_OFF + 1024)        // 97KB -> still 2 CTAs/SM

#define NTILES (128 * 16 * NH * 2)        // 40960
#define PERSIST_CTAS 304                  // 2 per SM x 152 SMs (GB300)

#define ZB_BLOCKS  320
#define H1_BLOCKS  (NH * BSZ / 8)             // 20480
#define WT_BLOCKS  ((DD/64) * (DD/64) * NH * 2)  // 20480
#define PREP_BLOCKS (ZB_BLOCKS + H1_BLOCKS + WT_BLOCKS)

// ---------------- device scratch (no allocation allowed) ----------------
__device__ __align__(16) __half g_H1  [(size_t)NH * BSZ * DD];   // h1 fp16, [h][m][k]
__device__ __align__(16) __half g_W21T[(size_t)NH * DD * DD];    // W21^T fp16, [h][e][k]
__device__ __align__(16) __half g_W22T[(size_t)NH * DD * DD];    // W22^T fp16, [h][e][k]
__device__ __align__(16) float g_s31[NH * BSZ * 2];
__device__ __align__(16) float g_s32[NH * BSZ * 2];

// ---------------- helpers ----------------
__device__ __forceinline__ uint32_t smem_u32(const void* p) {
    uint32_t a;
    asm("{ .reg .u64 t; cvta.to.shared.u64 t, %1; cvt.u32.u64 %0, t; }" : "=r"(a) : "l"(p));
    return a;
}
__device__ __forceinline__ void cp16(uint32_t saddr, const void* g) {
    asm volatile("cp.async.cg.shared.global [%0], [%1], 16;" :: "r"(saddr), "l"(g));
}
__device__ __forceinline__ void cp_commit() { asm volatile("cp.async.commit_group;" ::: "memory"); }
__device__ __forceinline__ void cp_wait1()  { asm volatile("cp.async.wait_group 1;" ::: "memory"); }
__device__ __forceinline__ void ldsm4(uint32_t* r, uint32_t addr) {
    asm volatile("ldmatrix.sync.aligned.m8n8.x4.shared.b16 {%0,%1,%2,%3}, [%4];"
                 : "=r"(r[0]), "=r"(r[1]), "=r"(r[2]), "=r"(r[3]) : "r"(addr));
}
__device__ __forceinline__ void mma16816(float* c, const uint32_t* a, const uint32_t* b) {
    asm volatile(
        "mma.sync.aligned.m16n8k16.row.col.f32.f16.f16.f32 "
        "{%0,%1,%2,%3}, {%4,%5,%6,%7}, {%8,%9}, {%0,%1,%2,%3};"
        : "+f"(c[0]), "+f"(c[1]), "+f"(c[2]), "+f"(c[3])
        : "r"(a[0]), "r"(a[1]), "r"(a[2]), "r"(a[3]), "r"(b[0]), "r"(b[1]));
}
#define SW128(off) ((off) ^ (((off) >> 3) & 0x70))

// one cp.async stage (A 16KB + B 16KB) + commit
__device__ __forceinline__ void issue_stage(uint32_t sbase, int bufi,
                                            const __half* Ap, const __half* Bq,
                                            int k0, int t, int lcol) {
    const uint32_t sb_ = sbase + (uint32_t)bufi * STAGE_BYTES;
    #pragma unroll
    for (int i_ = 0; i_ < 8; i_++) {
        const int row_ = (i_ * 128 + t) >> 3;
        const uint32_t so_ = SW128((uint32_t)(row_ * 128 + lcol * 2));
        cp16(sb_ + so_,         Ap + (size_t)row_ * DD + k0 + lcol);
        cp16(sb_ + 16384 + so_, Bq + (size_t)row_ * DD + k0 + lcol);
    }
    cp_commit();
}

// ---------------- merged prep: scratch zero + H1 compute + W2 transpose-convert ----------------
__global__ __launch_bounds__(256, 4) void prep_kernel(
    const float* __restrict__ x, const float* __restrict__ W1, const float* __restrict__ b1,
    const float* __restrict__ W21, const float* __restrict__ W22)
{
    __shared__ float ts[64][65];
    __shared__ float4 sx[8];
    const int t = threadIdx.x;

    if (blockIdx.x < ZB_BLOCKS) {
        const int i = blockIdx.x * 256 + t;
        const float4 z = make_float4(0.f, 0.f, 0.f, 0.f);
        ((float4*)g_s31)[i] = z;
        ((float4*)g_s32)[i] = z;
    } else if (blockIdx.x < ZB_BLOCKS + H1_BLOCKS) {
        const int bi = blockIdx.x - ZB_BLOCKS;
        const int h  = bi >> 11;
        const int m0 = (bi & 2047) * 8;

        if (t < 8) sx[t] = *(const float4*)(x + (size_t)(m0 + t) * 4);
        __syncthreads();

        const float* W1h = W1 + ((size_t)h * 4) * DD + t * 8;
        const float* b1h = b1 + (size_t)h * DD + t * 8;

        float w[4][8], bb[8];
        #pragma unroll
        for (int f = 0; f < 4; f++) {
            float4 wa = *(const float4*)(W1h + (size_t)f * DD);
            float4 wb = *(const float4*)(W1h + (size_t)f * DD + 4);
            w[f][0]=wa.x; w[f][1]=wa.y; w[f][2]=wa.z; w[f][3]=wa.w;
            w[f][4]=wb.x; w[f][5]=wb.y; w[f][6]=wb.z; w[f][7]=wb.w;
        }
        {
            float4 ba = *(const float4*)(b1h);
            float4 bc = *(const float4*)(b1h + 4);
            bb[0]=ba.x; bb[1]=ba.y; bb[2]=ba.z; bb[3]=ba.w;
            bb[4]=bc.x; bb[5]=bc.y; bb[6]=bc.z; bb[7]=bc.w;
        }

        __half* outp = g_H1 + ((size_t)h * BSZ + m0) * DD + (size_t)t * 8;
        #pragma unroll
        for (int mi = 0; mi < 8; mi++) {
            const float4 xv = sx[mi];
            float r[8];
            #pragma unroll
            for (int j = 0; j < 8; j++) {
                float v = fmaf(xv.x, w[0][j], bb[j]);
                v = fmaf(xv.y, w[1][j], v);
                v = fmaf(xv.z, w[2][j], v);
                v = fmaf(xv.w, w[3][j], v);
                r[j] = fmaxf(v, 0.f);
            }
            __half2 o[4];
            #pragma unroll
            for (int j = 0; j < 4; j++)
                o[j] = __floats2half2_rn(r[2*j], r[2*j+1]);
            *(uint4*)(outp + (size_t)mi * DD) = *(uint4*)o;
        }
    } else {
        const int widx = blockIdx.x - (ZB_BLOCKS + H1_BLOCKS);
        const int e0 = (widx & 31) * 64;
        const int k0 = ((widx >> 5) & 31) * 64;
        const int hb = widx >> 10;
        const int h = hb >> 1;
        const float* W = (hb & 1) ? W22 : W21;
        __half* WT = (hb & 1) ? g_W22T : g_W21T;
        W  += (size_t)h * DD * DD;
        WT += (size_t)h * DD * DD;

        const int tx = t & 15;
        const int ty = t >> 4;

        #pragma unroll
        for (int r = 0; r < 4; r++) {
            const float4 v = *(const float4*)(W + (size_t)(k0 + ty + r*16) * DD + e0 + tx*4);
            ts[ty + r*16][tx*4 + 0] = v.x;
            ts[ty + r*16][tx*4 + 1] = v.y;
            ts[ty + r*16][tx*4 + 2] = v.z;
            ts[ty + r*16][tx*4 + 3] = v.w;
        }
        __syncthreads();
        #pragma unroll
        for (int r = 0; r < 4; r++) {
            const int e = ty + r*16;
            const float a0 = ts[tx*4 + 0][e];
            const float a1 = ts[tx*4 + 1][e];
            const float a2 = ts[tx*4 + 2][e];
            const float a3 = ts[tx*4 + 3][e];
            __half2 h01 = __floats2half2_rn(a0, a1);
            __half2 h23 = __floats2half2_rn(a2, a3);
            uint2 o;
            o.x = *(uint32_t*)&h01;
            o.y = *(uint32_t*)&h23;
            *(uint2*)(WT + (size_t)(e0 + e) * DD + k0 + tx*4) = o;
        }
    }
}

// ---------------- persistent HMMA GEMM + fused projection ----------------
// Tiles strided by gridDim; cp.async groups stream continuously across tile
// boundaries (next tile's stages 0/1 issued during current tile's last stages,
// so fill overlaps drain + epilogue). Inner ks/LDSM/MMA body identical to R5.
__global__ __launch_bounds__(128, 2) void gemm_kernel(
    const float* __restrict__ b21, const float* __restrict__ b22,
    const float* __restrict__ W31, const float* __restrict__ W32)
{
    extern __shared__ char smem[];
    const uint32_t sbase = smem_u32(smem);
    const int t = threadIdx.x, warp = t >> 5, lane = t & 31;
    const int wm = warp >> 1, wn = warp & 1;        // 2 x 2 warp grid
    const int lcol = (t & 7) * 8;

    int tile = blockIdx.x;
    int m0 = (tile & 127) * BM;
    int e0 = ((tile >> 7) & 15) * BN;
    int h  = tile >> 12;
    int br = (tile >> 11) & 1;

    const __half* A  = g_H1 + ((size_t)h * BSZ + m0) * DD;
    const __half* Bp = (br ? g_W22T : g_W21T) + ((size_t)h * DD + e0) * DD;

    issue_stage(sbase, 0, A, Bp, 0,  t, lcol);
    issue_stage(sbase, 1, A, Bp, BK, t, lcol);
    int iss = 2, cons = 0;

    for (;;) {
        const int nextTile = tile + PERSIST_CTAS;
        const bool hasNext = nextTile < NTILES;
        const __half *An = A, *Bn = Bp;
        int nm0 = 0, ne0 = 0, nh = 0, nbr = 0;
        if (hasNext) {
            nm0 = (nextTile & 127) * BM;
            ne0 = ((nextTile >> 7) & 15) * BN;
            nh  = nextTile >> 12;
            nbr = (nextTile >> 11) & 1;
            An = g_H1 + ((size_t)nh * BSZ + nm0) * DD;
            Bn = (nbr ? g_W22T : g_W21T) + ((size_t)nh * DD + ne0) * DD;
        }

        float acc[4][8][4];
        #pragma unroll
        for (int i = 0; i < 4; i++)
            #pragma unroll
            for (int j = 0; j < 8; j++)
                #pragma unroll
                for (int q = 0; q < 4; q++) acc[i][j][q] = 0.f;

        for (int s = 0; s < NS; s++) {
            cp_wait1();
            __syncthreads();
            if (s + 2 < NS)
                issue_stage(sbase, iss, A, Bp, (s + 2) * BK, t, lcol);
            else if (hasNext)
                issue_stage(sbase, iss, An, Bn, (s + 2 - NS) * BK, t, lcol);
            else
                cp_commit();   // empty group keeps the wait_group count structure
            iss = (iss == 2) ? 0 : iss + 1;

            const uint32_t sb = sbase + (uint32_t)cons * STAGE_BYTES;
            #pragma unroll
            for (int ks = 0; ks < 4; ks++) {
                const int kb = ks * 16;
                uint32_t a[4][4], b[4][4];
                #pragma unroll
                for (int mi = 0; mi < 4; mi++) {
                    const int row = wm * 64 + mi * 16 + (lane & 15);
                    const int kc  = kb + (lane >> 4) * 8;
                    ldsm4(a[mi], sb + SW128((uint32_t)(row * 128 + kc * 2)));
                }
                #pragma unroll
                for (int g = 0; g < 4; g++) {
                    const int nrow = wn * 64 + g * 16 + (lane & 7) + ((lane >> 4) << 3);
                    const int kc   = kb + ((lane >> 3) & 1) * 8;
                    ldsm4(b[g], sb + 16384 + SW128((uint32_t)(nrow * 128 + kc * 2)));
                }
                #pragma unroll
                for (int mi = 0; mi < 4; mi++)
                    #pragma unroll
                    for (int ni = 0; ni < 8; ni++)
                        mma16816(acc[mi][ni], a[mi], &b[ni >> 1][(ni & 1) * 2]);
            }
            cons = (cons == 2) ? 0 : cons + 1;
        }

        // ---- epilogue (dedicated red buffer; overlaps next tile's in-flight fills) ----
        const float* bias = (br ? b22 : b21) + (size_t)h * DD;
        const float* Wp   = (br ? W32 : W31) + (size_t)h * DD * 2;
        float* sc  = br ? g_s32 : g_s31;
        float* red = (float*)(smem + RED_OFF);

        __syncthreads();
        red[t] = 0.f;
        red[t + 128] = 0.f;
        __syncthreads();

        float p[4][4];
        #pragma unroll
        for (int mi = 0; mi < 4; mi++)
            #pragma unroll
            for (int q = 0; q < 4; q++) p[mi][q] = 0.f;

        #pragma unroll
        for (int ni = 0; ni < 8; ni++) {
            const int e = e0 + wn * 64 + ni * 8 + 2 * (lane & 3);
            const float2 bb = *(const float2*)(bias + e);
            const float4 ww = *(const float4*)(Wp + 2 * e);
            #pragma unroll
            for (int mi = 0; mi < 4; mi++) {
                const float v0 = fmaxf(acc[mi][ni][0] + bb.x, 0.f);
                const float v1 = fmaxf(acc[mi][ni][1] + bb.y, 0.f);
                const float v2 = fmaxf(acc[mi][ni][2] + bb.x, 0.f);
                const float v3 = fmaxf(acc[mi][ni][3] + bb.y, 0.f);
                p[mi][0] = fmaf(v0, ww.x, fmaf(v1, ww.z, p[mi][0]));
                p[mi][1] = fmaf(v0, ww.y, fmaf(v1, ww.w, p[mi][1]));
                p[mi][2] = fmaf(v2, ww.x, fmaf(v3, ww.z, p[mi][2]));
                p[mi][3] = fmaf(v2, ww.y, fmaf(v3, ww.w, p[mi][3]));
            }
        }
        #pragma unroll
        for (int mi = 0; mi < 4; mi++) {
            #pragma unroll
            for (int d = 1; d <= 2; d <<= 1) {
                p[mi][0] += __shfl_xor_sync(0xffffffffu, p[mi][0], d);
                p[mi][1] += __shfl_xor_sync(0xffffffffu, p[mi][1], d);
                p[mi][2] += __shfl_xor_sync(0xffffffffu, p[mi][2], d);
                p[mi][3] += __shfl_xor_sync(0xffffffffu, p[mi][3], d);
            }
            if ((lane & 3) == 0) {
                const int r0 = wm * 64 + mi * 16 + (lane >> 2);
                atomicAdd(&red[r0 * 2 + 0], p[mi][0]);
                atomicAdd(&red[r0 * 2 + 1], p[mi][1]);
                atomicAdd(&red[(r0 + 8) * 2 + 0], p[mi][2]);
                atomicAdd(&red[(r0 + 8) * 2 + 1], p[mi][3]);
            }
        }
        __syncthreads();
        atomicAdd(&sc[((size_t)h * BSZ + m0 + t) * 2 + 0], red[t * 2 + 0]);
        atomicAdd(&sc[((size_t)h * BSZ + m0 + t) * 2 + 1], red[t * 2 + 1]);
        __syncthreads();   // red reuse barrier for the next tile

        if (!hasNext) break;
        tile = nextTile; m0 = nm0; e0 = ne0; h = nh; br = nbr; A = An; Bp = Bn;
    }
}

// ---------------- CBF-QP + softmax head mix ----------------
__global__ __launch_bounds__(256) void abnet_final_kernel(
    const float* __restrict__ x,
    const float* __restrict__ b31, const float* __restrict__ b32,
    const float* __restrict__ wt,
    const float* __restrict__ mean, const float* __restrict__ stdv,
    float* __restrict__ out)
{
    const int b = blockIdx.x * blockDim.x + threadIdx.x;
    if (b >= BSZ) return;

    float wv[NH];
    float mx = -1e30f;
    #pragma unroll
    for (int h = 0; h < NH; h++) { wv[h] = wt[h]; mx = fmaxf(mx, wv[h]); }
    float s = 0.f;
    #pragma unroll
    for (int h = 0; h < NH; h++) { wv[h] = expf(wv[h] - mx); s += wv[h]; }
    const float inv = 1.f / s;

    const float4 xv = *(const float4*)(x + (size_t)b * 4);
    const float px = xv.x * stdv[0] + mean[0];
    const float py = xv.y * stdv[1] + mean[1];
    const float th = xv.z * stdv[2] + mean[2];
    const float v  = xv.w * stdv[3] + mean[3];

    const float dx = px - 40.0f;
    const float dy = py - 15.0f;
    const float st = sinf(th);
    const float ct = cosf(th);
    const float barrier = dx * dx + dy * dy - 36.0f;
    const float bdot = 2.f * dx * v * ct + 2.f * dy * v * st;
    const float Lf2b = 2.f * v * v;
    const float G0 = 2.f * dx * v * st - 2.f * dy * v * ct;   // -LgLfbu1
    const float G1 = -2.f * dx * ct - 2.f * dy * st;          // -LgLfbu2
    const float GG = G0 * G0 + G1 * G1;

    float o0 = 0.f, o1 = 0.f;
    #pragma unroll
    for (int h = 0; h < NH; h++) {
        const size_t base = ((size_t)h * BSZ + b) * 2;
        const float x310 = g_s31[base + 0] + b31[h * 2 + 0];
        const float x311 = g_s31[base + 1] + b31[h * 2 + 1];
        const float p0   = g_s32[base + 0] + b32[h * 2 + 0];
        const float p1   = g_s32[base + 1] + b32[h * 2 + 1];
        const float x320 = 4.f / (1.f + expf(-p0));
        const float x321 = 4.f / (1.f + expf(-p1));
        const float hr  = Lf2b + (x320 + x321) * bdot + x320 * x321 * barrier;
        const float Gu  = G0 * x310 + G1 * x311;
        const float lam = fmaxf(Gu - hr, 0.f) / GG;
        const float wh  = wv[h] * inv;
        o0 += wh * (x310 - lam * G0);
        o1 += wh * (x311 - lam * G1);
    }
    out[(size_t)b * 2 + 0] = o0;
    out[(size_t)b * 2 + 1] = o1;
}

// ---------------- launch ----------------
extern "C" void kernel_launch(void* const* d_in, const int* in_sizes, int n_in,
                              void* d_out, int out_size)
{
    const float* x    = (const float*)d_in[0];
    const float* W1   = (const float*)d_in[1];
    const float* b1   = (const float*)d_in[2];
    const float* W21  = (const float*)d_in[3];
    const float* b21  = (const float*)d_in[4];
    const float* W22  = (const float*)d_in[5];
    const float* b22  = (const float*)d_in[6];
    const float* W31  = (const float*)d_in[7];
    const float* b31  = (const float*)d_in[8];
    const float* W32  = (const float*)d_in[9];
    const float* b32  = (const float*)d_in[10];
    const float* wt   = (const float*)d_in[11];
    const float* mean = (const float*)d_in[12];
    const float* stdv = (const float*)d_in[13];
    float* out = (float*)d_out;

    static bool inited = false;
    if (!inited) {
        cudaFuncSetAttribute(gemm_kernel, cudaFuncAttributeMaxDynamicSharedMemorySize, GEMM_SMEM);
        inited = true;
    }

    // merged prep: scratch zero + H1 + W2^T in one launch
    prep_kernel<<<PREP_BLOCKS, 256>>>(x, W1, b1, W21, W22);

    // persistent GEMM: 2 CTAs per SM
    gemm_kernel<<<PERSIST_CTAS, 128, GEMM_SMEM>>>(b21, b22, W31, W32);

    abnet_final_kernel<<<BSZ / 256, 256>>>(x, b31, b32, wt, mean, stdv, out);
}

// round 16
// speedup vs baseline: 1.0162x; 1.0162x over previous
#include <cuda_runtime.h>
#include <cuda_fp16.h>
#include <math.h>
#include <stdint.h>

// ---------------- problem constants ----------------
#define NH   10
#define BSZ  16384
#define DD   2048      // D1 == D21 == D22
#define BM   128
#define BN   128
#define BK   64
#define NS   (DD/BK)   // 32 k-stages
#define STAGE_BYTES 32768   // A 16KB + B 16KB per stage
#define SMEM_TOTAL  (3 * STAGE_BYTES)   // 96KB -> 2 CTAs/SM

#define ZB_BLOCKS  320                        // zero scratch: 81920 float4 per array
#define H1_BLOCKS  (NH * BSZ / 8)             // 20480 (one block = h + 8 m-rows)
#define WT_BLOCKS  ((DD/64) * (DD/64) * NH * 2)  // 20480 (64x64 tiles)
#define PREP_BLOCKS (ZB_BLOCKS + H1_BLOCKS + WT_BLOCKS)

// ---------------- device scratch (no allocation allowed) ----------------
__device__ __align__(16) __half g_H1  [(size_t)NH * BSZ * DD];   // h1 fp16, [h][m][k]
__device__ __align__(16) __half g_W21T[(size_t)NH * DD * DD];    // W21^T fp16, [h][e][k]
__device__ __align__(16) __half g_W22T[(size_t)NH * DD * DD];    // W22^T fp16, [h][e][k]
__device__ __align__(16) float g_s31[NH * BSZ * 2];
__device__ __align__(16) float g_s32[NH * BSZ * 2];

// ---------------- helpers ----------------
__device__ __forceinline__ uint32_t smem_u32(const void* p) {
    uint32_t a;
    asm("{ .reg .u64 t; cvta.to.shared.u64 t, %1; cvt.u32.u64 %0, t; }" : "=r"(a) : "l"(p));
    return a;
}
__device__ __forceinline__ void cp16(uint32_t saddr, const void* g) {
    asm volatile("cp.async.cg.shared.global [%0], [%1], 16;" :: "r"(saddr), "l"(g));
}
__device__ __forceinline__ void cp_commit() { asm volatile("cp.async.commit_group;" ::: "memory"); }
__device__ __forceinline__ void cp_wait1()  { asm volatile("cp.async.wait_group 1;" ::: "memory"); }
__device__ __forceinline__ void cp_wait0()  { asm volatile("cp.async.wait_group 0;" ::: "memory"); }
__device__ __forceinline__ void ldsm4(uint32_t* r, uint32_t addr) {
    asm volatile("ldmatrix.sync.aligned.m8n8.x4.shared.b16 {%0,%1,%2,%3}, [%4];"
                 : "=r"(r[0]), "=r"(r[1]), "=r"(r[2]), "=r"(r[3]) : "r"(addr));
}
__device__ __forceinline__ void mma16816(float* c, const uint32_t* a, const uint32_t* b) {
    asm volatile(
        "mma.sync.aligned.m16n8k16.row.col.f32.f16.f16.f32 "
        "{%0,%1,%2,%3}, {%4,%5,%6,%7}, {%8,%9}, {%0,%1,%2,%3};"
        : "+f"(c[0]), "+f"(c[1]), "+f"(c[2]), "+f"(c[3])
        : "r"(a[0]), "r"(a[1]), "r"(a[2]), "r"(a[3]), "r"(b[0]), "r"(b[1]));
}
#define SW128(off) ((off) ^ (((off) >> 3) & 0x70))

// ---------------- merged prep: scratch zero + H1 compute + W2 transpose-convert ----------------
__global__ __launch_bounds__(256, 4) void prep_kernel(
    const float* __restrict__ x, const float* __restrict__ W1, const float* __restrict__ b1,
    const float* __restrict__ W21, const float* __restrict__ W22)
{
    __shared__ float ts[64][65];
    __shared__ float4 sx[8];
    const int t = threadIdx.x;

    if (blockIdx.x < ZB_BLOCKS) {
        // ---- zero the partial-sum scratch (1 float4 per thread per array) ----
        const int i = blockIdx.x * 256 + t;   // < 81920 = NH*BSZ*2/4
        const float4 z = make_float4(0.f, 0.f, 0.f, 0.f);
        ((float4*)g_s31)[i] = z;
        ((float4*)g_s32)[i] = z;
    } else if (blockIdx.x < ZB_BLOCKS + H1_BLOCKS) {
        // ---- H1 = relu(x @ W1 + b1) fp16; one block = (h, 8 m-rows), thread = k8 ----
        const int bi = blockIdx.x - ZB_BLOCKS;
        const int h  = bi >> 11;               // BSZ/8 = 2048 blocks per head
        const int m0 = (bi & 2047) * 8;

        if (t < 8) sx[t] = *(const float4*)(x + (size_t)(m0 + t) * 4);
        __syncthreads();

        const float* W1h = W1 + ((size_t)h * 4) * DD + t * 8;
        const float* b1h = b1 + (size_t)h * DD + t * 8;

        // load weights/bias once into registers
        float w[4][8], bb[8];
        #pragma unroll
        for (int f = 0; f < 4; f++) {
            float4 wa = *(const float4*)(W1h + (size_t)f * DD);
            float4 wb = *(const float4*)(W1h + (size_t)f * DD + 4);
            w[f][0]=wa.x; w[f][1]=wa.y; w[f][2]=wa.z; w[f][3]=wa.w;
            w[f][4]=wb.x; w[f][5]=wb.y; w[f][6]=wb.z; w[f][7]=wb.w;
        }
        {
            float4 ba = *(const float4*)(b1h);
            float4 bc = *(const float4*)(b1h + 4);
            bb[0]=ba.x; bb[1]=ba.y; bb[2]=ba.z; bb[3]=ba.w;
            bb[4]=bc.x; bb[5]=bc.y; bb[6]=bc.z; bb[7]=bc.w;
        }

        __half* outp = g_H1 + ((size_t)h * BSZ + m0) * DD + (size_t)t * 8;
        #pragma unroll
        for (int mi = 0; mi < 8; mi++) {
            const float4 xv = sx[mi];
            float r[8];
            #pragma unroll
            for (int j = 0; j < 8; j++) {
                float v = fmaf(xv.x, w[0][j], bb[j]);
                v = fmaf(xv.y, w[1][j], v);
                v = fmaf(xv.z, w[2][j], v);
                v = fmaf(xv.w, w[3][j], v);
                r[j] = fmaxf(v, 0.f);
            }
            __half2 o[4];
            #pragma unroll
            for (int j = 0; j < 4; j++)
                o[j] = __floats2half2_rn(r[2*j], r[2*j+1]);
            *(uint4*)(outp + (size_t)mi * DD) = *(uint4*)o;
        }
    } else {
        // ---- W2x^T fp16 transpose-convert, 64x64 tiles, vectorized ----
        const int widx = blockIdx.x - (ZB_BLOCKS + H1_BLOCKS);
        const int e0 = (widx & 31) * 64;
        const int k0 = ((widx >> 5) & 31) * 64;
        const int hb = widx >> 10;
        const int h = hb >> 1;
        const float* W = (hb & 1) ? W22 : W21;
        __half* WT = (hb & 1) ? g_W22T : g_W21T;
        W  += (size_t)h * DD * DD;
        WT += (size_t)h * DD * DD;

        const int tx = t & 15;        // 0..15
        const int ty = t >> 4;        // 0..15

        #pragma unroll
        for (int r = 0; r < 4; r++) {
            const float4 v = *(const float4*)(W + (size_t)(k0 + ty + r*16) * DD + e0 + tx*4);
            ts[ty + r*16][tx*4 + 0] = v.x;
            ts[ty + r*16][tx*4 + 1] = v.y;
            ts[ty + r*16][tx*4 + 2] = v.z;
            ts[ty + r*16][tx*4 + 3] = v.w;
        }
        __syncthreads();
        #pragma unroll
        for (int r = 0; r < 4; r++) {
            const int e = ty + r*16;
            const float a0 = ts[tx*4 + 0][e];
            const float a1 = ts[tx*4 + 1][e];
            const float a2 = ts[tx*4 + 2][e];
            const float a3 = ts[tx*4 + 3][e];
            __half2 h01 = __floats2half2_rn(a0, a1);
            __half2 h23 = __floats2half2_rn(a2, a3);
            uint2 o;
            o.x = *(uint32_t*)&h01;
            o.y = *(uint32_t*)&h23;
            *(uint2*)(WT + (size_t)(e0 + e) * DD + k0 + tx*4) = o;
        }
    }
}

// ---------------- HMMA GEMM + fused projection (R5 verbatim) ----------------
// C[m,e] = H1[h,m,:] @ W2T[h,e,:]^T ; v = relu(C + b2[e]); scratch += v @ W3[:,0:2]
// 128 threads, BM=128 x BN=128, warp grid 2x2, 64x64 per-warp tile, 2 CTAs/SM.
__global__ __launch_bounds__(128, 2) void gemm_kernel(
    const float* __restrict__ b21, const float* __restrict__ b22,
    const float* __restrict__ W31, const float* __restrict__ W32)
{
    extern __shared__ char smem[];
    const uint32_t sbase = smem_u32(smem);
    const int t = threadIdx.x, warp = t >> 5, lane = t & 31;
    const int wm = warp >> 1, wn = warp & 1;        // 2 x 2 warp grid

    const int m0 = blockIdx.x * BM, e0 = blockIdx.y * BN;
    const int hb = blockIdx.z, h = hb >> 1, br = hb & 1;

    const __half* __restrict__ A  = g_H1 + ((size_t)h * BSZ + m0) * DD;
    const __half* __restrict__ Bp = (br ? g_W22T : g_W21T) + ((size_t)h * DD + e0) * DD;
    const float*  __restrict__ bias = (br ? b22 : b21) + (size_t)h * DD;
    const float*  __restrict__ Wp   = (br ? W32 : W31) + (size_t)h * DD * 2;
    float* __restrict__ sc = br ? g_s32 : g_s31;

    float acc[4][8][4];
    #pragma unroll
    for (int i = 0; i < 4; i++)
        #pragma unroll
        for (int j = 0; j < 8; j++)
            #pragma unroll
            for (int q = 0; q < 4; q++) acc[i][j][q] = 0.f;

    const int lcol = (t & 7) * 8;   // halves within 64-wide k-chunk

    // stage: A 128x64 halves (16KB) + B 128x64 halves (16KB); 128 threads -> 8+8 cp16 each
    #define ISSUE(s) do {                                                           \
        const int k0_ = (s) * BK;                                                   \
        const uint32_t sb_ = sbase + ((s) % 3) * STAGE_BYTES;                       \
        _Pragma("unroll")                                                           \
        for (int i_ = 0; i_ < 8; i_++) {                                            \
            const int row_ = (i_ * 128 + t) >> 3;                                   \
            const uint32_t so_ = SW128((uint32_t)(row_ * 128 + lcol * 2));          \
            cp16(sb_ + so_,         A  + (size_t)row_ * DD + k0_ + lcol);           \
            cp16(sb_ + 16384 + so_, Bp + (size_t)row_ * DD + k0_ + lcol);           \
        }                                                                           \
        cp_commit();                                                                \
    } while (0)

    ISSUE(0);
    ISSUE(1);

    for (int s = 0; s < NS; s++) {
        if (s == NS - 1) cp_wait0(); else cp_wait1();
        __syncthreads();
        if (s + 2 < NS) ISSUE(s + 2);

        const uint32_t sb = sbase + (s % 3) * STAGE_BYTES;
        #pragma unroll
        for (int ks = 0; ks < 4; ks++) {
            const int kb = ks * 16;
            uint32_t a[4][4], b[4][4];
            #pragma unroll
            for (int mi = 0; mi < 4; mi++) {
                const int row = wm * 64 + mi * 16 + (lane & 15);
                const int kc  = kb + (lane >> 4) * 8;
                ldsm4(a[mi], sb + SW128((uint32_t)(row * 128 + kc * 2)));
            }
            #pragma unroll
            for (int g = 0; g < 4; g++) {
                const int nrow = wn * 64 + g * 16 + (lane & 7) + ((lane >> 4) << 3);
                const int kc   = kb + ((lane >> 3) & 1) * 8;
                ldsm4(b[g], sb + 16384 + SW128((uint32_t)(nrow * 128 + kc * 2)));
            }
            #pragma unroll
            for (int mi = 0; mi < 4; mi++)
                #pragma unroll
                for (int ni = 0; ni < 8; ni++)
                    mma16816(acc[mi][ni], a[mi], &b[ni >> 1][(ni & 1) * 2]);
        }
    }
    __syncthreads();

    // ---- epilogue: bias + relu + project to C=2, reduce ----
    float* red = (float*)smem;      // 128 rows x 2 chans
    red[t] = 0.f;
    red[t + 128] = 0.f;
    __syncthreads();

    float p[4][4];
    #pragma unroll
    for (int mi = 0; mi < 4; mi++)
        #pragma unroll
        for (int q = 0; q < 4; q++) p[mi][q] = 0.f;

    #pragma unroll
    for (int ni = 0; ni < 8; ni++) {
        const int e = e0 + wn * 64 + ni * 8 + 2 * (lane & 3);
        const float2 bb = *(const float2*)(bias + e);
        const float4 ww = *(const float4*)(Wp + 2 * e);
        #pragma unroll
        for (int mi = 0; mi < 4; mi++) {
            const float v0 = fmaxf(acc[mi][ni][0] + bb.x, 0.f);
            const float v1 = fmaxf(acc[mi][ni][1] + bb.y, 0.f);
            const float v2 = fmaxf(acc[mi][ni][2] + bb.x, 0.f);
            const float v3 = fmaxf(acc[mi][ni][3] + bb.y, 0.f);
            p[mi][0] = fmaf(v0, ww.x, fmaf(v1, ww.z, p[mi][0]));
            p[mi][1] = fmaf(v0, ww.y, fmaf(v1, ww.w, p[mi][1]));
            p[mi][2] = fmaf(v2, ww.x, fmaf(v3, ww.z, p[mi][2]));
            p[mi][3] = fmaf(v2, ww.y, fmaf(v3, ww.w, p[mi][3]));
        }
    }
    #pragma unroll
    for (int mi = 0; mi < 4; mi++) {
        #pragma unroll
        for (int d = 1; d <= 2; d <<= 1) {
            p[mi][0] += __shfl_xor_sync(0xffffffffu, p[mi][0], d);
            p[mi][1] += __shfl_xor_sync(0xffffffffu, p[mi][1], d);
            p[mi][2] += __shfl_xor_sync(0xffffffffu, p[mi][2], d);
            p[mi][3] += __shfl_xor_sync(0xffffffffu, p[mi][3], d);
        }
        if ((lane & 3) == 0) {
            const int r0 = wm * 64 + mi * 16 + (lane >> 2);
            atomicAdd(&red[r0 * 2 + 0], p[mi][0]);
            atomicAdd(&red[r0 * 2 + 1], p[mi][1]);
            atomicAdd(&red[(r0 + 8) * 2 + 0], p[mi][2]);
            atomicAdd(&red[(r0 + 8) * 2 + 1], p[mi][3]);
        }
    }
    __syncthreads();
    atomicAdd(&sc[((size_t)h * BSZ + m0 + t) * 2 + 0], red[t * 2 + 0]);
    atomicAdd(&sc[((size_t)h * BSZ + m0 + t) * 2 + 1], red[t * 2 + 1]);
}

// ---------------- CBF-QP + softmax head mix ----------------
__global__ __launch_bounds__(256) void abnet_final_kernel(
    const float* __restrict__ x,
    const float* __restrict__ b31, const float* __restrict__ b32,
    const float* __restrict__ wt,
    const float* __restrict__ mean, const float* __restrict__ stdv,
    float* __restrict__ out)
{
    const int b = blockIdx.x * blockDim.x + threadIdx.x;
    if (b >= BSZ) return;

    float wv[NH];
    float mx = -1e30f;
    #pragma unroll
    for (int h = 0; h < NH; h++) { wv[h] = wt[h]; mx = fmaxf(mx, wv[h]); }
    float s = 0.f;
    #pragma unroll
    for (int h = 0; h < NH; h++) { wv[h] = __expf(wv[h] - mx); s += wv[h]; }
    const float inv = 1.f / s;

    const float4 xv = *(const float4*)(x + (size_t)b * 4);
    const float px = xv.x * stdv[0] + mean[0];
    const float py = xv.y * stdv[1] + mean[1];
    const float th = xv.z * stdv[2] + mean[2];
    const float v  = xv.w * stdv[3] + mean[3];

    const float dx = px - 40.0f;
    const float dy = py - 15.0f;
    const float st = sinf(th);
    const float ct = cosf(th);
    const float barrier = dx * dx + dy * dy - 36.0f;
    const float bdot = 2.f * dx * v * ct + 2.f * dy * v * st;
    const float Lf2b = 2.f * v * v;
    const float G0 = 2.f * dx * v * st - 2.f * dy * v * ct;   // -LgLfbu1
    const float G1 = -2.f * dx * ct - 2.f * dy * st;          // -LgLfbu2
    const float GG = G0 * G0 + G1 * G1;

    float o0 = 0.f, o1 = 0.f;
    #pragma unroll
    for (int h = 0; h < NH; h++) {
        const size_t base = ((size_t)h * BSZ + b) * 2;
        const float x310 = g_s31[base + 0] + b31[h * 2 + 0];
        const float x311 = g_s31[base + 1] + b31[h * 2 + 1];
        const float p0   = g_s32[base + 0] + b32[h * 2 + 0];
        const float p1   = g_s32[base + 1] + b32[h * 2 + 1];
        const float x320 = 4.f / (1.f + __expf(-p0));
        const float x321 = 4.f / (1.f + __expf(-p1));
        const float hr  = Lf2b + (x320 + x321) * bdot + x320 * x321 * barrier;
        const float Gu  = G0 * x310 + G1 * x311;
        const float lam = fmaxf(Gu - hr, 0.f) / GG;
        const float wh  = wv[h] * inv;
        o0 += wh * (x310 - lam * G0);
        o1 += wh * (x311 - lam * G1);
    }
    out[(size_t)b * 2 + 0] = o0;
    out[(size_t)b * 2 + 1] = o1;
}

// ---------------- launch ----------------
extern "C" void kernel_launch(void* const* d_in, const int* in_sizes, int n_in,
                              void* d_out, int out_size)
{
    const float* x    = (const float*)d_in[0];
    const float* W1   = (const float*)d_in[1];
    const float* b1   = (const float*)d_in[2];
    const float* W21  = (const float*)d_in[3];
    const float* b21  = (const float*)d_in[4];
    const float* W22  = (const float*)d_in[5];
    const float* b22  = (const float*)d_in[6];
    const float* W31  = (const float*)d_in[7];
    const float* b31  = (const float*)d_in[8];
    const float* W32  = (const float*)d_in[9];
    const float* b32  = (const float*)d_in[10];
    const float* wt   = (const float*)d_in[11];
    const float* mean = (const float*)d_in[12];
    const float* stdv = (const float*)d_in[13];
    float* out = (float*)d_out;

    static bool inited = false;
    if (!inited) {
        cudaFuncSetAttribute(gemm_kernel, cudaFuncAttributeMaxDynamicSharedMemorySize, SMEM_TOTAL);
        cudaFuncSetAttribute(gemm_kernel, cudaFuncAttributePreferredSharedMemoryCarveout,
                             cudaSharedmemCarveoutMaxShared);
        inited = true;
    }

    // merged prep: scratch zero + H1 + W2^T in one launch
    prep_kernel<<<PREP_BLOCKS, 256>>>(x, W1, b1, W21, W22);

    dim3 grid(BSZ / BM, DD / BN, NH * 2);
    gemm_kernel<<<grid, 128, SMEM_TOTAL>>>(b21, b22, W31, W32);

    abnet_final_kernel<<<BSZ / 256, 256>>>(x, b31, b32, wt, mean, stdv, out);
}